// round 15
// baseline (speedup 1.0000x reference)
#include <cuda_runtime.h>
#include <cuda_fp16.h>
#include <math.h>
#include <stdint.h>

#define BB 4
#define SS 2048
#define HH 16
#define DD 64
#define HID 1024
#define BS (BB*SS)
#define LOG2E 1.4426950408889634f

// ---------------- scratch (device globals: allocation-free rule) ------------
__device__ __half g_xh[BS*DD];           // x split (compensated operand)
__device__ __half g_xl[BS*DD];
__device__ __half g_WTh[3*HID*DD];       // QKV W^T hi only: [which][n][k]
__device__ __half g_WoTh[DD*HID];        // Wo^T hi only: [n][k]
// Q pre-scaled by (1/sqrt(D)) * log2(e). All [b,h,s,d]. All hi-only.
__device__ __half g_Qh[BB*HH*SS*DD];
__device__ __half g_Kh[BB*HH*SS*DD];
__device__ __half g_Vh[BB*HH*SS*DD];
__device__ __half g_attnh[BS*HID];       // attn out split, [B,S,HID]
__device__ __half g_attnl[BS*HID];

// ---------------- helpers ---------------------------------------------------
static __device__ __forceinline__ uint32_t smem_u32(const void* p) {
    return (uint32_t)__cvta_generic_to_shared(p);
}
static __device__ __forceinline__ void ldm_x4(uint32_t* r, uint32_t addr) {
    asm volatile("ldmatrix.sync.aligned.m8n8.x4.shared.b16 {%0,%1,%2,%3}, [%4];"
                 : "=r"(r[0]), "=r"(r[1]), "=r"(r[2]), "=r"(r[3]) : "r"(addr));
}
static __device__ __forceinline__ void ldm_x4_t(uint32_t* r, uint32_t addr) {
    asm volatile("ldmatrix.sync.aligned.m8n8.x4.trans.shared.b16 {%0,%1,%2,%3}, [%4];"
                 : "=r"(r[0]), "=r"(r[1]), "=r"(r[2]), "=r"(r[3]) : "r"(addr));
}
static __device__ __forceinline__ void mma16816(float* c,
                                                uint32_t a0, uint32_t a1, uint32_t a2, uint32_t a3,
                                                uint32_t b0, uint32_t b1) {
    asm volatile(
        "mma.sync.aligned.m16n8k16.row.col.f32.f16.f16.f32 "
        "{%0,%1,%2,%3}, {%4,%5,%6,%7}, {%8,%9}, {%0,%1,%2,%3};"
        : "+f"(c[0]), "+f"(c[1]), "+f"(c[2]), "+f"(c[3])
        : "r"(a0), "r"(a1), "r"(a2), "r"(a3), "r"(b0), "r"(b1));
}
static __device__ __forceinline__ uint32_t pack2h(float f0, float f1) {
    __half2 t = __halves2half2(__float2half_rn(f0), __float2half_rn(f1));
    return *reinterpret_cast<uint32_t*>(&t);
}
static __device__ __forceinline__ float ex2(float x) {
    float y;
    asm("ex2.approx.ftz.f32 %0, %1;" : "=f"(y) : "f"(x));
    return y;
}
static __device__ __forceinline__ uint32_t h2ex2(uint32_t x) {
    uint32_t y;
    asm("ex2.approx.f16x2 %0, %1;" : "=r"(y) : "r"(x));
    return y;
}
#define ONES2H 0x3C003C00u   // half2(1.0, 1.0)
#define CPA(dst, src) asm volatile("cp.async.ca.shared.global [%0], [%1], 16;" :: "r"(dst), "l"(src))
#define CPC()   asm volatile("cp.async.commit_group;" ::: "memory")
#define CPW0()  asm volatile("cp.async.wait_group 0;" ::: "memory")

// ---------------------------------------------------------------------------
// Kernel 0: prep — split x to fp16 hi/lo; W^T, Wo^T to fp16 hi.
// ---------------------------------------------------------------------------
#define NX (BS*DD)          // 524288
#define NW (3*HID*DD)       // 196608
#define NWO (DD*HID)        // 65536
__global__ void prep_kernel(const float* __restrict__ x,
                            const float* __restrict__ Wq,
                            const float* __restrict__ Wk,
                            const float* __restrict__ Wv,
                            const float* __restrict__ Wo) {
    for (int idx = blockIdx.x * blockDim.x + threadIdx.x; idx < NX + NW + NWO;
         idx += gridDim.x * blockDim.x) {
        if (idx < NX) {
            float f = x[idx];
            __half hi = __float2half_rn(f);
            g_xh[idx] = hi;
            g_xl[idx] = __float2half_rn(f - __half2float(hi));
        } else if (idx < NX + NW) {
            int r = idx - NX;
            int which = r >> 16;
            int t = r & 65535;
            int n = t >> 6, k = t & 63;
            const float* W = (which == 0) ? Wq : (which == 1) ? Wk : Wv;
            g_WTh[r] = __float2half_rn(W[k * HID + n]);
        } else {
            int r = idx - NX - NW;          // r = n*1024 + k
            int n = r >> 10, k = r & 1023;
            g_WoTh[r] = __float2half_rn(Wo[k * DD + n]);
        }
    }
}

// ---------------------------------------------------------------------------
// Kernel 1: QKV projection via HMMA: (xh+xl) @ Wh.  All outputs hi-only.
// grid = (BS/64, HID/64, 3), block = 128.
// ---------------------------------------------------------------------------
__global__ void __launch_bounds__(128) qkv_mma_kernel(const float* __restrict__ bq,
                                                      const float* __restrict__ bk,
                                                      const float* __restrict__ bv) {
    __shared__ __align__(16) char smem[3 * 9216];   // XH, XL, WH
    const uint32_t smb = smem_u32(smem);

    const int m0    = blockIdx.x * 64;
    const int h     = blockIdx.y;
    const int which = blockIdx.z;
    const int c0    = h * 64;

    const int tid  = threadIdx.x;
    const int w    = tid >> 5;
    const int lane = tid & 31;

    const float* bp = (which == 0) ? bq : (which == 1) ? bk : bv;

    for (int idx = tid; idx < 1536; idx += 128) {
        int arr = idx >> 9, rem = idx & 511, r = rem >> 3, ch = rem & 7;
        const __half* src;
        if      (arr == 0) src = g_xh  + (size_t)(m0 + r) * DD + ch * 8;
        else if (arr == 1) src = g_xl  + (size_t)(m0 + r) * DD + ch * 8;
        else               src = g_WTh + (size_t)which * HID * DD + (size_t)(c0 + r) * DD + ch * 8;
        *(uint4*)(smem + arr * 9216 + r * 144 + ch * 16) = *(const uint4*)src;
    }
    __syncthreads();

    uint32_t ah[4][4], al[4][4];
    {
        const uint32_t abase = smb + (uint32_t)((w * 16 + (lane & 15)) * 144 + (lane >> 4) * 16);
        #pragma unroll
        for (int kk = 0; kk < 4; kk++) {
            ldm_x4(ah[kk], abase + kk * 32);
            ldm_x4(al[kk], abase + kk * 32 + 9216);
        }
    }
    const uint32_t bbase = smb + 18432 +
        (uint32_t)(((lane & 7) + ((lane >> 4) & 1) * 8) * 144 + ((lane >> 3) & 1) * 16);

    float sacc[8][4];
    #pragma unroll
    for (int j = 0; j < 8; j++)
        #pragma unroll
        for (int e = 0; e < 4; e++) sacc[j][e] = 0.f;

    #pragma unroll
    for (int jj = 0; jj < 4; jj++) {
        #pragma unroll
        for (int kk = 0; kk < 4; kk++) {
            uint32_t bhr[4];
            ldm_x4(bhr, bbase + (uint32_t)(jj * 16 * 144 + kk * 32));
            mma16816(sacc[2*jj],   ah[kk][0], ah[kk][1], ah[kk][2], ah[kk][3], bhr[0], bhr[1]);
            mma16816(sacc[2*jj],   al[kk][0], al[kk][1], al[kk][2], al[kk][3], bhr[0], bhr[1]);
            mma16816(sacc[2*jj+1], ah[kk][0], ah[kk][1], ah[kk][2], ah[kk][3], bhr[2], bhr[3]);
            mma16816(sacc[2*jj+1], al[kk][0], al[kk][1], al[kk][2], al[kk][3], bhr[2], bhr[3]);
        }
    }

    const float scale = (which == 0) ? 0.125f * LOG2E : 1.0f;
    __half* Ah = (which == 0) ? g_Qh : (which == 1) ? g_Kh : g_Vh;
    const int b   = m0 >> 11;
    const int ss0 = m0 & 2047;
    const int r0  = w * 16 + (lane >> 2);
    const size_t base0 = (((size_t)b * HH + h) * SS + (ss0 + r0)) * DD;
    const size_t base1 = base0 + (size_t)8 * DD;
    #pragma unroll
    for (int j = 0; j < 8; j++) {
        const int c = j * 8 + 2 * (lane & 3);
        *(uint32_t*)&Ah[base0 + c] = pack2h((sacc[j][0] + bp[c0 + c]) * scale,
                                            (sacc[j][1] + bp[c0 + c + 1]) * scale);
        *(uint32_t*)&Ah[base1 + c] = pack2h((sacc[j][2] + bp[c0 + c]) * scale,
                                            (sacc[j][3] + bp[c0 + c + 1]) * scale);
    }
}

// ---------------------------------------------------------------------------
// Kernel 2: causal flash attention (fp16 HMMA, hi-only operands).
// R13 structure + single-sync double-buffered pipeline.
// 2 CTAs/SM.  grid = (S/128, H, B), block = 256.
// ---------------------------------------------------------------------------
#define SQH 0
#define SKV 18432            // two buffers of 36864 (KH, VH @ 18432 each)
#define ATTN_SMEM (18432 + 2*36864)   // 92160; x2 CTAs = 184320 < 227KB

__global__ void __launch_bounds__(256, 2) attn_kernel() {
    extern __shared__ char smem[];
    const uint32_t smb = smem_u32(smem);

    const int qt = gridDim.x - 1 - blockIdx.x;   // heavy tiles first
    const int h  = blockIdx.y;
    const int b  = blockIdx.z;
    const int q0 = qt * 128;

    const int tid  = threadIdx.x;
    const int w    = tid >> 5;
    const int lane = tid & 31;

    const size_t bh = (size_t)b * HH + h;
    const __half* Qh = g_Qh + (bh * SS + q0) * DD;
    const __half* Kh = g_Kh + bh * SS * DD;
    const __half* Vh = g_Vh + bh * SS * DD;

    const int ktmax = qt;   // 128-key tiles, kt <= qt

    // prefetch K/V tile 0 into buffer 0 (K: 128x64, V: 128x64)
    {
        const uint32_t base = smb + SKV;
        for (int idx = tid; idx < 2048; idx += 256) {
            int arr = idx >> 10, rem = idx & 1023, r = rem >> 3, ch = rem & 7;
            const __half* src = (arr == 0) ? (Kh + (size_t)r * DD + ch * 8)
                                           : (Vh + (size_t)r * DD + ch * 8);
            CPA(base + arr * 18432 + r * 144 + ch * 16, src);
        }
        CPC();
    }

    // load Q tile (hi only)
    for (int idx = tid; idx < 1024; idx += 256) {
        int r = idx >> 3, ch = idx & 7;
        *(uint4*)(smem + SQH + r * 144 + ch * 16) = *(const uint4*)(Qh + (size_t)r * DD + ch * 8);
    }
    __syncthreads();

    uint32_t qh[4][4];
    {
        const uint32_t qbase = smb + SQH + (uint32_t)((w * 16 + (lane & 15)) * 144 + (lane >> 4) * 16);
        #pragma unroll
        for (int kk = 0; kk < 4; kk++) ldm_x4(qh[kk], qbase + kk * 32);
    }

    float o[8][4];
    #pragma unroll
    for (int j = 0; j < 8; j++)
        #pragma unroll
        for (int e = 0; e < 4; e++) o[j][e] = 0.f;
    float lacc[4] = {0.f, 0.f, 0.f, 0.f};   // row-sum accumulator (B=ones MMA)
    float m0 = -1e30f, m1 = -1e30f;

    const int rg0  = q0 + w * 16 + (lane >> 2);
    const int wmax = q0 + w * 16 + 15;

    const uint32_t klane = (uint32_t)(((lane & 7) + ((lane >> 4) & 1) * 8) * 144 + ((lane >> 3) & 1) * 16);
    const uint32_t vlane = (uint32_t)(((lane & 7) + ((lane >> 3) & 1) * 8) * 144 + ((lane >> 4) & 1) * 16);

    for (int kt = 0; kt <= ktmax; kt++) {
        const int buf = kt & 1;

        // wait for current buffer (prefetched at kt-1, overlapped with compute)
        CPW0();
        __syncthreads();   // single sync: cp.async visible cross-warp AND
                           // all warps done reading buf^1 (read during kt-1)

        // issue prefetch for next tile into the other buffer (overlaps compute)
        if (kt < ktmax) {
            const int nk0 = (kt + 1) * 128;
            const uint32_t base = smb + SKV + (buf ^ 1) * 36864;
            for (int idx = tid; idx < 2048; idx += 256) {
                int arr = idx >> 10, rem = idx & 1023, r = rem >> 3, ch = rem & 7;
                const __half* src = (arr == 0) ? (Kh + (size_t)(nk0 + r) * DD + ch * 8)
                                               : (Vh + (size_t)(nk0 + r) * DD + ch * 8);
                CPA(base + arr * 18432 + r * 144 + ch * 16, src);
            }
            CPC();
        }

        const uint32_t kvb = smb + SKV + buf * 36864;

        #pragma unroll
        for (int hf = 0; hf < 2; hf++) {
            const int khalf0 = kt * 128 + hf * 64;
            int jjn = (wmax >= khalf0) ? (((wmax - khalf0) >> 4) + 1) : 0;
            if (jjn > 4) jjn = 4;
            if (jjn == 0) continue;

            const uint32_t kbase = kvb + (uint32_t)(hf * 64 * 144) + klane;
            const uint32_t vbase = kvb + 18432 + (uint32_t)(hf * 64 * 144) + vlane;

            // ---- S = Qh Kh^T ----
            float sacc[8][4];
            #pragma unroll
            for (int j = 0; j < 8; j++)
                #pragma unroll
                for (int e = 0; e < 4; e++) sacc[j][e] = 0.f;

            #pragma unroll
            for (int jj = 0; jj < 4; jj++) {
                if (jj >= jjn) break;
                #pragma unroll
                for (int kk = 0; kk < 4; kk++) {
                    uint32_t bhr[4];
                    ldm_x4(bhr, kbase + (uint32_t)(jj * 16 * 144 + kk * 32));
                    mma16816(sacc[2*jj],   qh[kk][0], qh[kk][1], qh[kk][2], qh[kk][3], bhr[0], bhr[1]);
                    mma16816(sacc[2*jj+1], qh[kk][0], qh[kk][1], qh[kk][2], qh[kk][3], bhr[2], bhr[3]);
                }
            }
            // blank untouched groups (so max is unaffected; exp gives 0)
            #pragma unroll
            for (int j = 0; j < 8; j++)
                if (j >= 2 * jjn) {
                    sacc[j][0] = sacc[j][1] = sacc[j][2] = sacc[j][3] = -1e30f;
                }

            // ---- causal element mask (only if this half straddles diag) ----
            if (khalf0 + 63 > rg0) {
                #pragma unroll
                for (int j = 0; j < 8; j++) {
                    const int cbase = khalf0 + j * 8 + 2 * (lane & 3);
                    if (cbase     > rg0)     sacc[j][0] = -1e30f;
                    if (cbase + 1 > rg0)     sacc[j][1] = -1e30f;
                    if (cbase     > rg0 + 8) sacc[j][2] = -1e30f;
                    if (cbase + 1 > rg0 + 8) sacc[j][3] = -1e30f;
                }
            }

            // ---- online softmax (base-2), exp in half2 ----
            float mx0 = -1e30f, mx1 = -1e30f;
            #pragma unroll
            for (int j = 0; j < 8; j++) {
                mx0 = fmaxf(mx0, fmaxf(sacc[j][0], sacc[j][1]));
                mx1 = fmaxf(mx1, fmaxf(sacc[j][2], sacc[j][3]));
            }
            mx0 = fmaxf(mx0, __shfl_xor_sync(0xffffffffu, mx0, 1));
            mx0 = fmaxf(mx0, __shfl_xor_sync(0xffffffffu, mx0, 2));
            mx1 = fmaxf(mx1, __shfl_xor_sync(0xffffffffu, mx1, 1));
            mx1 = fmaxf(mx1, __shfl_xor_sync(0xffffffffu, mx1, 2));

            const float nm0 = fmaxf(m0, mx0);
            const float nm1 = fmaxf(m1, mx1);
            const float corr0 = ex2(m0 - nm0);
            const float corr1 = ex2(m1 - nm1);
            m0 = nm0; m1 = nm1;

            uint32_t ph[8][2];
            #pragma unroll
            for (int j = 0; j < 8; j++) {
                ph[j][0] = h2ex2(pack2h(sacc[j][0] - nm0, sacc[j][1] - nm0));
                ph[j][1] = h2ex2(pack2h(sacc[j][2] - nm1, sacc[j][3] - nm1));
            }

            // rescale running O and l
            #pragma unroll
            for (int j = 0; j < 8; j++) {
                o[j][0] *= corr0; o[j][1] *= corr0;
                o[j][2] *= corr1; o[j][3] *= corr1;
            }
            lacc[0] *= corr0; lacc[1] *= corr0;
            lacc[2] *= corr1; lacc[3] *= corr1;

            // ---- O += Ph Vh;  l += Ph @ ones ----
            #pragma unroll
            for (int kk = 0; kk < 4; kk++) {
                if (kk >= jjn) break;
                mma16816(lacc, ph[2*kk][0], ph[2*kk][1], ph[2*kk+1][0], ph[2*kk+1][1], ONES2H, ONES2H);
                #pragma unroll
                for (int dd = 0; dd < 4; dd++) {
                    uint32_t vh[4];
                    ldm_x4_t(vh, vbase + (uint32_t)(kk * 16 * 144 + dd * 32));
                    mma16816(o[2*dd],   ph[2*kk][0], ph[2*kk][1], ph[2*kk+1][0], ph[2*kk+1][1], vh[0], vh[1]);
                    mma16816(o[2*dd+1], ph[2*kk][0], ph[2*kk][1], ph[2*kk+1][0], ph[2*kk+1][1], vh[2], vh[3]);
                }
            }
        }
    }

    // ---- epilogue: normalize, split hi/lo, write fp16 [B,S,HID] ----
    const float inv0 = 1.f / lacc[0];
    const float inv1 = 1.f / lacc[2];
    const size_t db0 = ((size_t)b * SS + rg0) * HID + h * 64;
    const size_t db1 = db0 + (size_t)8 * HID;
    #pragma unroll
    for (int j = 0; j < 8; j++) {
        const int c = j * 8 + 2 * (lane & 3);
        {
            float v0 = o[j][0] * inv0, v1 = o[j][1] * inv0;
            __half h0 = __float2half_rn(v0), h1 = __float2half_rn(v1);
            *(uint32_t*)&g_attnh[db0 + c] = pack2h(v0, v1);
            *(uint32_t*)&g_attnl[db0 + c] = pack2h(v0 - __half2float(h0), v1 - __half2float(h1));
        }
        {
            float v0 = o[j][2] * inv1, v1 = o[j][3] * inv1;
            __half h0 = __float2half_rn(v0), h1 = __float2half_rn(v1);
            *(uint32_t*)&g_attnh[db1 + c] = pack2h(v0, v1);
            *(uint32_t*)&g_attnl[db1 + c] = pack2h(v0 - __half2float(h0), v1 - __half2float(h1));
        }
    }
}

// ---------------------------------------------------------------------------
// Kernel 3: output projection via HMMA: (Ah+Al) @ Woh + bo.
// Single-sync pipeline.  grid = BS/64, block = 128.  K=1024, 16 steps.
// ---------------------------------------------------------------------------
// per buffer: AH, AL, WH @ 9216 each = 27648; two buffers = 55296.
#define OPROJ_SMEM (2 * 27648)
__global__ void __launch_bounds__(128) oproj_mma_kernel(const float* __restrict__ bo,
                                                        float* __restrict__ out) {
    extern __shared__ char smem[];
    const uint32_t smb = smem_u32(smem);

    const int m0  = blockIdx.x * 64;
    const int tid = threadIdx.x;
    const int w   = tid >> 5;
    const int lane = tid & 31;

    {
        const uint32_t base = smb;
        for (int idx = tid; idx < 1536; idx += 128) {
            int arr = idx >> 9, rem = idx & 511, r = rem >> 3, ch = rem & 7;
            const __half* src;
            if      (arr == 0) src = g_attnh + (size_t)(m0 + r) * HID + ch * 8;
            else if (arr == 1) src = g_attnl + (size_t)(m0 + r) * HID + ch * 8;
            else               src = g_WoTh + (size_t)r * HID + ch * 8;
            CPA(base + arr * 9216 + r * 144 + ch * 16, src);
        }
        CPC();
    }

    float sacc[8][4];
    #pragma unroll
    for (int j = 0; j < 8; j++)
        #pragma unroll
        for (int e = 0; e < 4; e++) sacc[j][e] = 0.f;

    const uint32_t a_off = (uint32_t)((w * 16 + (lane & 15)) * 144 + (lane >> 4) * 16);
    const uint32_t b_off = (uint32_t)(((lane & 7) + ((lane >> 4) & 1) * 8) * 144 + ((lane >> 3) & 1) * 16);

    for (int kt = 0; kt < 16; kt++) {
        const int buf = kt & 1;

        CPW0();
        __syncthreads();   // single sync per step

        if (kt < 15) {
            const int nk0 = (kt + 1) * 64;
            const uint32_t base = smb + (buf ^ 1) * 27648;
            for (int idx = tid; idx < 1536; idx += 128) {
                int arr = idx >> 9, rem = idx & 511, r = rem >> 3, ch = rem & 7;
                const __half* src;
                if      (arr == 0) src = g_attnh + (size_t)(m0 + r) * HID + nk0 + ch * 8;
                else if (arr == 1) src = g_attnl + (size_t)(m0 + r) * HID + nk0 + ch * 8;
                else               src = g_WoTh + (size_t)r * HID + nk0 + ch * 8;
                CPA(base + arr * 9216 + r * 144 + ch * 16, src);
            }
            CPC();
        }

        const uint32_t bb = smb + buf * 27648;
        const uint32_t abase = bb + a_off;
        const uint32_t bbase = bb + 18432 + b_off;

        #pragma unroll
        for (int kk = 0; kk < 4; kk++) {
            uint32_t ah[4], al[4];
            ldm_x4(ah, abase + kk * 32);
            ldm_x4(al, abase + kk * 32 + 9216);
            #pragma unroll
            for (int jj = 0; jj < 4; jj++) {
                uint32_t bhr[4];
                ldm_x4(bhr, bbase + (uint32_t)(jj * 16 * 144 + kk * 32));
                mma16816(sacc[2*jj],   ah[0], ah[1], ah[2], ah[3], bhr[0], bhr[1]);
                mma16816(sacc[2*jj],   al[0], al[1], al[2], al[3], bhr[0], bhr[1]);
                mma16816(sacc[2*jj+1], ah[0], ah[1], ah[2], ah[3], bhr[2], bhr[3]);
                mma16816(sacc[2*jj+1], al[0], al[1], al[2], al[3], bhr[2], bhr[3]);
            }
        }
    }

    const int r0 = w * 16 + (lane >> 2);
    #pragma unroll
    for (int j = 0; j < 8; j++) {
        const int c = j * 8 + 2 * (lane & 3);
        out[(size_t)(m0 + r0) * DD + c]     = sacc[j][0] + bo[c];
        out[(size_t)(m0 + r0) * DD + c + 1] = sacc[j][1] + bo[c + 1];
        out[(size_t)(m0 + r0 + 8) * DD + c]     = sacc[j][2] + bo[c];
        out[(size_t)(m0 + r0 + 8) * DD + c + 1] = sacc[j][3] + bo[c + 1];
    }
}

// ---------------------------------------------------------------------------
extern "C" void kernel_launch(void* const* d_in, const int* in_sizes, int n_in,
                              void* d_out, int out_size) {
    (void)in_sizes; (void)n_in; (void)out_size;
    const float* x  = (const float*)d_in[0];
    const float* Wq = (const float*)d_in[1];
    const float* bq = (const float*)d_in[2];
    const float* Wk = (const float*)d_in[3];
    const float* bk = (const float*)d_in[4];
    const float* Wv = (const float*)d_in[5];
    const float* bv = (const float*)d_in[6];
    const float* Wo = (const float*)d_in[7];
    const float* bo = (const float*)d_in[8];
    float* out = (float*)d_out;

    prep_kernel<<<1024, 256>>>(x, Wq, Wk, Wv, Wo);

    qkv_mma_kernel<<<dim3(BS / 64, HID / 64, 3), 128>>>(bq, bk, bv);

    cudaFuncSetAttribute(attn_kernel, cudaFuncAttributeMaxDynamicSharedMemorySize, ATTN_SMEM);
    attn_kernel<<<dim3(SS / 128, HH, BB), 256, ATTN_SMEM>>>();

    cudaFuncSetAttribute(oproj_mma_kernel, cudaFuncAttributeMaxDynamicSharedMemorySize, OPROJ_SMEM);
    oproj_mma_kernel<<<BS / 64, 128, OPROJ_SMEM>>>(bo, out);
}

// round 16
// speedup vs baseline: 1.6017x; 1.6017x over previous
#include <cuda_runtime.h>
#include <cuda_fp16.h>
#include <math.h>
#include <stdint.h>

#define BB 4
#define SS 2048
#define HH 16
#define DD 64
#define HID 1024
#define BS (BB*SS)
#define LOG2E 1.4426950408889634f

// ---------------- scratch (device globals: allocation-free rule) ------------
__device__ __half g_xh[BS*DD];           // x split (compensated operand)
__device__ __half g_xl[BS*DD];
__device__ __half g_WTh[3*HID*DD];       // QKV W^T hi only: [which][n][k]
__device__ __half g_WoTh[DD*HID];        // Wo^T hi only: [n][k]
// Q pre-scaled by (1/sqrt(D)) * log2(e). All [b,h,s,d]. All hi-only.
__device__ __half g_Qh[BB*HH*SS*DD];
__device__ __half g_Kh[BB*HH*SS*DD];
__device__ __half g_Vh[BB*HH*SS*DD];
__device__ __half g_attnh[BS*HID];       // attn out (fp16, hi only), [B,S,HID]

// ---------------- helpers ---------------------------------------------------
static __device__ __forceinline__ uint32_t smem_u32(const void* p) {
    return (uint32_t)__cvta_generic_to_shared(p);
}
static __device__ __forceinline__ void ldm_x4(uint32_t* r, uint32_t addr) {
    asm volatile("ldmatrix.sync.aligned.m8n8.x4.shared.b16 {%0,%1,%2,%3}, [%4];"
                 : "=r"(r[0]), "=r"(r[1]), "=r"(r[2]), "=r"(r[3]) : "r"(addr));
}
static __device__ __forceinline__ void ldm_x4_t(uint32_t* r, uint32_t addr) {
    asm volatile("ldmatrix.sync.aligned.m8n8.x4.trans.shared.b16 {%0,%1,%2,%3}, [%4];"
                 : "=r"(r[0]), "=r"(r[1]), "=r"(r[2]), "=r"(r[3]) : "r"(addr));
}
static __device__ __forceinline__ void mma16816(float* c,
                                                uint32_t a0, uint32_t a1, uint32_t a2, uint32_t a3,
                                                uint32_t b0, uint32_t b1) {
    asm volatile(
        "mma.sync.aligned.m16n8k16.row.col.f32.f16.f16.f32 "
        "{%0,%1,%2,%3}, {%4,%5,%6,%7}, {%8,%9}, {%0,%1,%2,%3};"
        : "+f"(c[0]), "+f"(c[1]), "+f"(c[2]), "+f"(c[3])
        : "r"(a0), "r"(a1), "r"(a2), "r"(a3), "r"(b0), "r"(b1));
}
static __device__ __forceinline__ uint32_t pack2h(float f0, float f1) {
    __half2 t = __halves2half2(__float2half_rn(f0), __float2half_rn(f1));
    return *reinterpret_cast<uint32_t*>(&t);
}
static __device__ __forceinline__ float ex2(float x) {
    float y;
    asm("ex2.approx.ftz.f32 %0, %1;" : "=f"(y) : "f"(x));
    return y;
}
static __device__ __forceinline__ uint32_t h2ex2(uint32_t x) {
    uint32_t y;
    asm("ex2.approx.f16x2 %0, %1;" : "=r"(y) : "r"(x));
    return y;
}
#define ONES2H 0x3C003C00u   // half2(1.0, 1.0)
#define CPA(dst, src) asm volatile("cp.async.ca.shared.global [%0], [%1], 16;" :: "r"(dst), "l"(src))
#define CPC()   asm volatile("cp.async.commit_group;" ::: "memory")
#define CPW1()  asm volatile("cp.async.wait_group 1;" ::: "memory")
#define CPW0()  asm volatile("cp.async.wait_group 0;" ::: "memory")

// ---------------------------------------------------------------------------
// Kernel 0: prep — split x to fp16 hi/lo; W^T, Wo^T to fp16 hi.
// ---------------------------------------------------------------------------
#define NX (BS*DD)          // 524288
#define NW (3*HID*DD)       // 196608
#define NWO (DD*HID)        // 65536
__global__ void prep_kernel(const float* __restrict__ x,
                            const float* __restrict__ Wq,
                            const float* __restrict__ Wk,
                            const float* __restrict__ Wv,
                            const float* __restrict__ Wo) {
    for (int idx = blockIdx.x * blockDim.x + threadIdx.x; idx < NX + NW + NWO;
         idx += gridDim.x * blockDim.x) {
        if (idx < NX) {
            float f = x[idx];
            __half hi = __float2half_rn(f);
            g_xh[idx] = hi;
            g_xl[idx] = __float2half_rn(f - __half2float(hi));
        } else if (idx < NX + NW) {
            int r = idx - NX;
            int which = r >> 16;
            int t = r & 65535;
            int n = t >> 6, k = t & 63;
            const float* W = (which == 0) ? Wq : (which == 1) ? Wk : Wv;
            g_WTh[r] = __float2half_rn(W[k * HID + n]);
        } else {
            int r = idx - NX - NW;          // r = n*1024 + k
            int n = r >> 10, k = r & 1023;
            g_WoTh[r] = __float2half_rn(Wo[k * DD + n]);
        }
    }
}

// ---------------------------------------------------------------------------
// Kernel 1: QKV projection via HMMA: (xh+xl) @ Wh.  All outputs hi-only.
// grid = (BS/64, HID/64, 3), block = 128.
// ---------------------------------------------------------------------------
__global__ void __launch_bounds__(128) qkv_mma_kernel(const float* __restrict__ bq,
                                                      const float* __restrict__ bk,
                                                      const float* __restrict__ bv) {
    __shared__ __align__(16) char smem[3 * 9216];   // XH, XL, WH
    const uint32_t smb = smem_u32(smem);

    const int m0    = blockIdx.x * 64;
    const int h     = blockIdx.y;
    const int which = blockIdx.z;
    const int c0    = h * 64;

    const int tid  = threadIdx.x;
    const int w    = tid >> 5;
    const int lane = tid & 31;

    const float* bp = (which == 0) ? bq : (which == 1) ? bk : bv;

    for (int idx = tid; idx < 1536; idx += 128) {
        int arr = idx >> 9, rem = idx & 511, r = rem >> 3, ch = rem & 7;
        const __half* src;
        if      (arr == 0) src = g_xh  + (size_t)(m0 + r) * DD + ch * 8;
        else if (arr == 1) src = g_xl  + (size_t)(m0 + r) * DD + ch * 8;
        else               src = g_WTh + (size_t)which * HID * DD + (size_t)(c0 + r) * DD + ch * 8;
        *(uint4*)(smem + arr * 9216 + r * 144 + ch * 16) = *(const uint4*)src;
    }
    __syncthreads();

    uint32_t ah[4][4], al[4][4];
    {
        const uint32_t abase = smb + (uint32_t)((w * 16 + (lane & 15)) * 144 + (lane >> 4) * 16);
        #pragma unroll
        for (int kk = 0; kk < 4; kk++) {
            ldm_x4(ah[kk], abase + kk * 32);
            ldm_x4(al[kk], abase + kk * 32 + 9216);
        }
    }
    const uint32_t bbase = smb + 18432 +
        (uint32_t)(((lane & 7) + ((lane >> 4) & 1) * 8) * 144 + ((lane >> 3) & 1) * 16);

    float sacc[8][4];
    #pragma unroll
    for (int j = 0; j < 8; j++)
        #pragma unroll
        for (int e = 0; e < 4; e++) sacc[j][e] = 0.f;

    #pragma unroll
    for (int jj = 0; jj < 4; jj++) {
        #pragma unroll
        for (int kk = 0; kk < 4; kk++) {
            uint32_t bhr[4];
            ldm_x4(bhr, bbase + (uint32_t)(jj * 16 * 144 + kk * 32));
            mma16816(sacc[2*jj],   ah[kk][0], ah[kk][1], ah[kk][2], ah[kk][3], bhr[0], bhr[1]);
            mma16816(sacc[2*jj],   al[kk][0], al[kk][1], al[kk][2], al[kk][3], bhr[0], bhr[1]);
            mma16816(sacc[2*jj+1], ah[kk][0], ah[kk][1], ah[kk][2], ah[kk][3], bhr[2], bhr[3]);
            mma16816(sacc[2*jj+1], al[kk][0], al[kk][1], al[kk][2], al[kk][3], bhr[2], bhr[3]);
        }
    }

    const float scale = (which == 0) ? 0.125f * LOG2E : 1.0f;
    __half* Ah = (which == 0) ? g_Qh : (which == 1) ? g_Kh : g_Vh;
    const int b   = m0 >> 11;
    const int ss0 = m0 & 2047;
    const int r0  = w * 16 + (lane >> 2);
    const size_t base0 = (((size_t)b * HH + h) * SS + (ss0 + r0)) * DD;
    const size_t base1 = base0 + (size_t)8 * DD;
    #pragma unroll
    for (int j = 0; j < 8; j++) {
        const int c = j * 8 + 2 * (lane & 3);
        *(uint32_t*)&Ah[base0 + c] = pack2h((sacc[j][0] + bp[c0 + c]) * scale,
                                            (sacc[j][1] + bp[c0 + c + 1]) * scale);
        *(uint32_t*)&Ah[base1 + c] = pack2h((sacc[j][2] + bp[c0 + c]) * scale,
                                            (sacc[j][3] + bp[c0 + c + 1]) * scale);
    }
}

// ---------------------------------------------------------------------------
// Kernel 2: causal flash attention (fp16 HMMA, hi-only operands).
// Exact R13 structure (proven 215 µs): 2 syncs/tile, CPW1 prefetch pattern.
// 2 CTAs/SM.  grid = (S/128, H, B), block = 256.
// ---------------------------------------------------------------------------
#define SQH 0
#define SKV 18432            // two buffers of 36864 (KH, VH @ 18432 each)
#define ATTN_SMEM (18432 + 2*36864)   // 92160; x2 CTAs = 184320 < 227KB

__global__ void __launch_bounds__(256, 2) attn_kernel() {
    extern __shared__ char smem[];
    const uint32_t smb = smem_u32(smem);

    const int qt = gridDim.x - 1 - blockIdx.x;   // heavy tiles first
    const int h  = blockIdx.y;
    const int b  = blockIdx.z;
    const int q0 = qt * 128;

    const int tid  = threadIdx.x;
    const int w    = tid >> 5;
    const int lane = tid & 31;

    const size_t bh = (size_t)b * HH + h;
    const __half* Qh = g_Qh + (bh * SS + q0) * DD;
    const __half* Kh = g_Kh + bh * SS * DD;
    const __half* Vh = g_Vh + bh * SS * DD;

    const int ktmax = qt;   // 128-key tiles, kt <= qt

    // prefetch K/V tile 0 into buffer 0 (K: 128x64, V: 128x64)
    {
        const uint32_t base = smb + SKV;
        for (int idx = tid; idx < 2048; idx += 256) {
            int arr = idx >> 10, rem = idx & 1023, r = rem >> 3, ch = rem & 7;
            const __half* src = (arr == 0) ? (Kh + (size_t)r * DD + ch * 8)
                                           : (Vh + (size_t)r * DD + ch * 8);
            CPA(base + arr * 18432 + r * 144 + ch * 16, src);
        }
        CPC();
    }

    // load Q tile (hi only)
    for (int idx = tid; idx < 1024; idx += 256) {
        int r = idx >> 3, ch = idx & 7;
        *(uint4*)(smem + SQH + r * 144 + ch * 16) = *(const uint4*)(Qh + (size_t)r * DD + ch * 8);
    }
    __syncthreads();

    uint32_t qh[4][4];
    {
        const uint32_t qbase = smb + SQH + (uint32_t)((w * 16 + (lane & 15)) * 144 + (lane >> 4) * 16);
        #pragma unroll
        for (int kk = 0; kk < 4; kk++) ldm_x4(qh[kk], qbase + kk * 32);
    }

    float o[8][4];
    #pragma unroll
    for (int j = 0; j < 8; j++)
        #pragma unroll
        for (int e = 0; e < 4; e++) o[j][e] = 0.f;
    float lacc[4] = {0.f, 0.f, 0.f, 0.f};   // row-sum accumulator (B=ones MMA)
    float m0 = -1e30f, m1 = -1e30f;

    const int rg0  = q0 + w * 16 + (lane >> 2);
    const int wmax = q0 + w * 16 + 15;

    const uint32_t klane = (uint32_t)(((lane & 7) + ((lane >> 4) & 1) * 8) * 144 + ((lane >> 3) & 1) * 16);
    const uint32_t vlane = (uint32_t)(((lane & 7) + ((lane >> 3) & 1) * 8) * 144 + ((lane >> 4) & 1) * 16);

    for (int kt = 0; kt <= ktmax; kt++) {
        const int buf = kt & 1;

        if (kt < ktmax) {
            const int nk0 = (kt + 1) * 128;
            const uint32_t base = smb + SKV + (buf ^ 1) * 36864;
            for (int idx = tid; idx < 2048; idx += 256) {
                int arr = idx >> 10, rem = idx & 1023, r = rem >> 3, ch = rem & 7;
                const __half* src = (arr == 0) ? (Kh + (size_t)(nk0 + r) * DD + ch * 8)
                                               : (Vh + (size_t)(nk0 + r) * DD + ch * 8);
                CPA(base + arr * 18432 + r * 144 + ch * 16, src);
            }
            CPC();
            CPW1();
        } else {
            CPW0();
        }
        __syncthreads();

        const uint32_t kvb = smb + SKV + buf * 36864;

        #pragma unroll
        for (int hf = 0; hf < 2; hf++) {
            const int khalf0 = kt * 128 + hf * 64;
            int jjn = (wmax >= khalf0) ? (((wmax - khalf0) >> 4) + 1) : 0;
            if (jjn > 4) jjn = 4;
            if (jjn == 0) continue;

            const uint32_t kbase = kvb + (uint32_t)(hf * 64 * 144) + klane;
            const uint32_t vbase = kvb + 18432 + (uint32_t)(hf * 64 * 144) + vlane;

            // ---- S = Qh Kh^T ----
            float sacc[8][4];
            #pragma unroll
            for (int j = 0; j < 8; j++)
                #pragma unroll
                for (int e = 0; e < 4; e++) sacc[j][e] = 0.f;

            #pragma unroll
            for (int jj = 0; jj < 4; jj++) {
                if (jj >= jjn) break;
                #pragma unroll
                for (int kk = 0; kk < 4; kk++) {
                    uint32_t bhr[4];
                    ldm_x4(bhr, kbase + (uint32_t)(jj * 16 * 144 + kk * 32));
                    mma16816(sacc[2*jj],   qh[kk][0], qh[kk][1], qh[kk][2], qh[kk][3], bhr[0], bhr[1]);
                    mma16816(sacc[2*jj+1], qh[kk][0], qh[kk][1], qh[kk][2], qh[kk][3], bhr[2], bhr[3]);
                }
            }
            // blank untouched groups (so max is unaffected; exp gives 0)
            #pragma unroll
            for (int j = 0; j < 8; j++)
                if (j >= 2 * jjn) {
                    sacc[j][0] = sacc[j][1] = sacc[j][2] = sacc[j][3] = -1e30f;
                }

            // ---- causal element mask (only if this half straddles diag) ----
            if (khalf0 + 63 > rg0) {
                #pragma unroll
                for (int j = 0; j < 8; j++) {
                    const int cbase = khalf0 + j * 8 + 2 * (lane & 3);
                    if (cbase     > rg0)     sacc[j][0] = -1e30f;
                    if (cbase + 1 > rg0)     sacc[j][1] = -1e30f;
                    if (cbase     > rg0 + 8) sacc[j][2] = -1e30f;
                    if (cbase + 1 > rg0 + 8) sacc[j][3] = -1e30f;
                }
            }

            // ---- online softmax (base-2), exp in half2 ----
            float mx0 = -1e30f, mx1 = -1e30f;
            #pragma unroll
            for (int j = 0; j < 8; j++) {
                mx0 = fmaxf(mx0, fmaxf(sacc[j][0], sacc[j][1]));
                mx1 = fmaxf(mx1, fmaxf(sacc[j][2], sacc[j][3]));
            }
            mx0 = fmaxf(mx0, __shfl_xor_sync(0xffffffffu, mx0, 1));
            mx0 = fmaxf(mx0, __shfl_xor_sync(0xffffffffu, mx0, 2));
            mx1 = fmaxf(mx1, __shfl_xor_sync(0xffffffffu, mx1, 1));
            mx1 = fmaxf(mx1, __shfl_xor_sync(0xffffffffu, mx1, 2));

            const float nm0 = fmaxf(m0, mx0);
            const float nm1 = fmaxf(m1, mx1);
            const float corr0 = ex2(m0 - nm0);
            const float corr1 = ex2(m1 - nm1);
            m0 = nm0; m1 = nm1;

            uint32_t ph[8][2];
            #pragma unroll
            for (int j = 0; j < 8; j++) {
                ph[j][0] = h2ex2(pack2h(sacc[j][0] - nm0, sacc[j][1] - nm0));
                ph[j][1] = h2ex2(pack2h(sacc[j][2] - nm1, sacc[j][3] - nm1));
            }

            // rescale running O and l
            #pragma unroll
            for (int j = 0; j < 8; j++) {
                o[j][0] *= corr0; o[j][1] *= corr0;
                o[j][2] *= corr1; o[j][3] *= corr1;
            }
            lacc[0] *= corr0; lacc[1] *= corr0;
            lacc[2] *= corr1; lacc[3] *= corr1;

            // ---- O += Ph Vh;  l += Ph @ ones ----
            #pragma unroll
            for (int kk = 0; kk < 4; kk++) {
                if (kk >= jjn) break;
                mma16816(lacc, ph[2*kk][0], ph[2*kk][1], ph[2*kk+1][0], ph[2*kk+1][1], ONES2H, ONES2H);
                #pragma unroll
                for (int dd = 0; dd < 4; dd++) {
                    uint32_t vh[4];
                    ldm_x4_t(vh, vbase + (uint32_t)(kk * 16 * 144 + dd * 32));
                    mma16816(o[2*dd],   ph[2*kk][0], ph[2*kk][1], ph[2*kk+1][0], ph[2*kk+1][1], vh[0], vh[1]);
                    mma16816(o[2*dd+1], ph[2*kk][0], ph[2*kk][1], ph[2*kk+1][0], ph[2*kk+1][1], vh[2], vh[3]);
                }
            }
        }
        __syncthreads();
    }

    // ---- epilogue: normalize, write fp16 (hi only) [B,S,HID] ----
    const float inv0 = 1.f / lacc[0];
    const float inv1 = 1.f / lacc[2];
    const size_t db0 = ((size_t)b * SS + rg0) * HID + h * 64;
    const size_t db1 = db0 + (size_t)8 * HID;
    #pragma unroll
    for (int j = 0; j < 8; j++) {
        const int c = j * 8 + 2 * (lane & 3);
        *(uint32_t*)&g_attnh[db0 + c] = pack2h(o[j][0] * inv0, o[j][1] * inv0);
        *(uint32_t*)&g_attnh[db1 + c] = pack2h(o[j][2] * inv1, o[j][3] * inv1);
    }
}

// ---------------------------------------------------------------------------
// Kernel 3: output projection via HMMA: Ah @ Woh + bo (single combo).
// R13 sync/prefetch pattern.  grid = BS/64, block = 128.  K=1024, 16 steps.
// ---------------------------------------------------------------------------
// per buffer: AH, WH @ 9216 each = 18432; two buffers = 36864.
#define OPROJ_SMEM (2 * 18432)
__global__ void __launch_bounds__(128) oproj_mma_kernel(const float* __restrict__ bo,
                                                        float* __restrict__ out) {
    extern __shared__ char smem[];
    const uint32_t smb = smem_u32(smem);

    const int m0  = blockIdx.x * 64;
    const int tid = threadIdx.x;
    const int w   = tid >> 5;
    const int lane = tid & 31;

    {
        const uint32_t base = smb;
        for (int idx = tid; idx < 1024; idx += 128) {
            int arr = idx >> 9, rem = idx & 511, r = rem >> 3, ch = rem & 7;
            const __half* src = (arr == 0) ? (g_attnh + (size_t)(m0 + r) * HID + ch * 8)
                                           : (g_WoTh + (size_t)r * HID + ch * 8);
            CPA(base + arr * 9216 + r * 144 + ch * 16, src);
        }
        CPC();
    }

    float sacc[8][4];
    #pragma unroll
    for (int j = 0; j < 8; j++)
        #pragma unroll
        for (int e = 0; e < 4; e++) sacc[j][e] = 0.f;

    const uint32_t a_off = (uint32_t)((w * 16 + (lane & 15)) * 144 + (lane >> 4) * 16);
    const uint32_t b_off = (uint32_t)(((lane & 7) + ((lane >> 4) & 1) * 8) * 144 + ((lane >> 3) & 1) * 16);

    for (int kt = 0; kt < 16; kt++) {
        const int buf = kt & 1;
        if (kt < 15) {
            const int nk0 = (kt + 1) * 64;
            const uint32_t base = smb + (buf ^ 1) * 18432;
            for (int idx = tid; idx < 1024; idx += 128) {
                int arr = idx >> 9, rem = idx & 511, r = rem >> 3, ch = rem & 7;
                const __half* src = (arr == 0) ? (g_attnh + (size_t)(m0 + r) * HID + nk0 + ch * 8)
                                               : (g_WoTh + (size_t)r * HID + nk0 + ch * 8);
                CPA(base + arr * 9216 + r * 144 + ch * 16, src);
            }
            CPC();
            CPW1();
        } else {
            CPW0();
        }
        __syncthreads();

        const uint32_t bb = smb + buf * 18432;
        const uint32_t abase = bb + a_off;
        const uint32_t bbase = bb + 9216 + b_off;

        #pragma unroll
        for (int kk = 0; kk < 4; kk++) {
            uint32_t ah[4];
            ldm_x4(ah, abase + kk * 32);
            #pragma unroll
            for (int jj = 0; jj < 4; jj++) {
                uint32_t bhr[4];
                ldm_x4(bhr, bbase + (uint32_t)(jj * 16 * 144 + kk * 32));
                mma16816(sacc[2*jj],   ah[0], ah[1], ah[2], ah[3], bhr[0], bhr[1]);
                mma16816(sacc[2*jj+1], ah[0], ah[1], ah[2], ah[3], bhr[2], bhr[3]);
            }
        }
        __syncthreads();
    }

    const int r0 = w * 16 + (lane >> 2);
    #pragma unroll
    for (int j = 0; j < 8; j++) {
        const int c = j * 8 + 2 * (lane & 3);
        out[(size_t)(m0 + r0) * DD + c]     = sacc[j][0] + bo[c];
        out[(size_t)(m0 + r0) * DD + c + 1] = sacc[j][1] + bo[c + 1];
        out[(size_t)(m0 + r0 + 8) * DD + c]     = sacc[j][2] + bo[c];
        out[(size_t)(m0 + r0 + 8) * DD + c + 1] = sacc[j][3] + bo[c + 1];
    }
}

// ---------------------------------------------------------------------------
extern "C" void kernel_launch(void* const* d_in, const int* in_sizes, int n_in,
                              void* d_out, int out_size) {
    (void)in_sizes; (void)n_in; (void)out_size;
    const float* x  = (const float*)d_in[0];
    const float* Wq = (const float*)d_in[1];
    const float* bq = (const float*)d_in[2];
    const float* Wk = (const float*)d_in[3];
    const float* bk = (const float*)d_in[4];
    const float* Wv = (const float*)d_in[5];
    const float* bv = (const float*)d_in[6];
    const float* Wo = (const float*)d_in[7];
    const float* bo = (const float*)d_in[8];
    float* out = (float*)d_out;

    prep_kernel<<<1024, 256>>>(x, Wq, Wk, Wv, Wo);

    qkv_mma_kernel<<<dim3(BS / 64, HID / 64, 3), 128>>>(bq, bk, bv);

    cudaFuncSetAttribute(attn_kernel, cudaFuncAttributeMaxDynamicSharedMemorySize, ATTN_SMEM);
    attn_kernel<<<dim3(SS / 128, HH, BB), 256, ATTN_SMEM>>>();

    cudaFuncSetAttribute(oproj_mma_kernel, cudaFuncAttributeMaxDynamicSharedMemorySize, OPROJ_SMEM);
    oproj_mma_kernel<<<BS / 64, 128, OPROJ_SMEM>>>(bo, out);
}

// round 17
// speedup vs baseline: 1.6999x; 1.0613x over previous
#include <cuda_runtime.h>
#include <cuda_fp16.h>
#include <math.h>
#include <stdint.h>

#define BB 4
#define SS 2048
#define HH 16
#define DD 64
#define HID 1024
#define BS (BB*SS)
#define LOG2E 1.4426950408889634f

// ---------------- scratch (device globals: allocation-free rule) ------------
__device__ __half g_xh[BS*DD];           // x (fp16 hi only)
__device__ __half g_WTh[3*HID*DD];       // QKV W^T hi only: [which][n][k]
__device__ __half g_WoTh[DD*HID];        // Wo^T hi only: [n][k]
// Q pre-scaled by (1/sqrt(D)) * log2(e). All [b,h,s,d]. All hi-only.
__device__ __half g_Qh[BB*HH*SS*DD];
__device__ __half g_Kh[BB*HH*SS*DD];
__device__ __half g_Vh[BB*HH*SS*DD];
__device__ __half g_attnh[BS*HID];       // attn out (fp16, hi only), [B,S,HID]

// ---------------- helpers ---------------------------------------------------
static __device__ __forceinline__ uint32_t smem_u32(const void* p) {
    return (uint32_t)__cvta_generic_to_shared(p);
}
static __device__ __forceinline__ void ldm_x4(uint32_t* r, uint32_t addr) {
    asm volatile("ldmatrix.sync.aligned.m8n8.x4.shared.b16 {%0,%1,%2,%3}, [%4];"
                 : "=r"(r[0]), "=r"(r[1]), "=r"(r[2]), "=r"(r[3]) : "r"(addr));
}
static __device__ __forceinline__ void ldm_x4_t(uint32_t* r, uint32_t addr) {
    asm volatile("ldmatrix.sync.aligned.m8n8.x4.trans.shared.b16 {%0,%1,%2,%3}, [%4];"
                 : "=r"(r[0]), "=r"(r[1]), "=r"(r[2]), "=r"(r[3]) : "r"(addr));
}
static __device__ __forceinline__ void mma16816(float* c,
                                                uint32_t a0, uint32_t a1, uint32_t a2, uint32_t a3,
                                                uint32_t b0, uint32_t b1) {
    asm volatile(
        "mma.sync.aligned.m16n8k16.row.col.f32.f16.f16.f32 "
        "{%0,%1,%2,%3}, {%4,%5,%6,%7}, {%8,%9}, {%0,%1,%2,%3};"
        : "+f"(c[0]), "+f"(c[1]), "+f"(c[2]), "+f"(c[3])
        : "r"(a0), "r"(a1), "r"(a2), "r"(a3), "r"(b0), "r"(b1));
}
static __device__ __forceinline__ uint32_t pack2h(float f0, float f1) {
    __half2 t = __halves2half2(__float2half_rn(f0), __float2half_rn(f1));
    return *reinterpret_cast<uint32_t*>(&t);
}
static __device__ __forceinline__ float ex2(float x) {
    float y;
    asm("ex2.approx.ftz.f32 %0, %1;" : "=f"(y) : "f"(x));
    return y;
}
static __device__ __forceinline__ uint32_t h2ex2(uint32_t x) {
    uint32_t y;
    asm("ex2.approx.f16x2 %0, %1;" : "=r"(y) : "r"(x));
    return y;
}
#define ONES2H 0x3C003C00u   // half2(1.0, 1.0)
#define CPA(dst, src) asm volatile("cp.async.ca.shared.global [%0], [%1], 16;" :: "r"(dst), "l"(src))
#define CPC()   asm volatile("cp.async.commit_group;" ::: "memory")
#define CPW1()  asm volatile("cp.async.wait_group 1;" ::: "memory")
#define CPW0()  asm volatile("cp.async.wait_group 0;" ::: "memory")

// ---------------------------------------------------------------------------
// Kernel 0: prep — x, W^T, Wo^T to fp16 hi.
// ---------------------------------------------------------------------------
#define NX (BS*DD)          // 524288
#define NW (3*HID*DD)       // 196608
#define NWO (DD*HID)        // 65536
__global__ void prep_kernel(const float* __restrict__ x,
                            const float* __restrict__ Wq,
                            const float* __restrict__ Wk,
                            const float* __restrict__ Wv,
                            const float* __restrict__ Wo) {
    for (int idx = blockIdx.x * blockDim.x + threadIdx.x; idx < NX + NW + NWO;
         idx += gridDim.x * blockDim.x) {
        if (idx < NX) {
            g_xh[idx] = __float2half_rn(x[idx]);
        } else if (idx < NX + NW) {
            int r = idx - NX;
            int which = r >> 16;
            int t = r & 65535;
            int n = t >> 6, k = t & 63;
            const float* W = (which == 0) ? Wq : (which == 1) ? Wk : Wv;
            g_WTh[r] = __float2half_rn(W[k * HID + n]);
        } else {
            int r = idx - NX - NW;          // r = n*1024 + k
            int n = r >> 10, k = r & 1023;
            g_WoTh[r] = __float2half_rn(Wo[k * DD + n]);
        }
    }
}

// ---------------------------------------------------------------------------
// Kernel 1: QKV projection via HMMA: xh @ Wh (single combo).
// grid = (BS/64, HID/64, 3), block = 128.
// ---------------------------------------------------------------------------
__global__ void __launch_bounds__(128) qkv_mma_kernel(const float* __restrict__ bq,
                                                      const float* __restrict__ bk,
                                                      const float* __restrict__ bv) {
    __shared__ __align__(16) char smem[2 * 9216];   // XH, WH
    const uint32_t smb = smem_u32(smem);

    const int m0    = blockIdx.x * 64;
    const int h     = blockIdx.y;
    const int which = blockIdx.z;
    const int c0    = h * 64;

    const int tid  = threadIdx.x;
    const int w    = tid >> 5;
    const int lane = tid & 31;

    const float* bp = (which == 0) ? bq : (which == 1) ? bk : bv;

    for (int idx = tid; idx < 1024; idx += 128) {
        int arr = idx >> 9, rem = idx & 511, r = rem >> 3, ch = rem & 7;
        const __half* src = (arr == 0)
            ? (g_xh  + (size_t)(m0 + r) * DD + ch * 8)
            : (g_WTh + (size_t)which * HID * DD + (size_t)(c0 + r) * DD + ch * 8);
        *(uint4*)(smem + arr * 9216 + r * 144 + ch * 16) = *(const uint4*)src;
    }
    __syncthreads();

    uint32_t ah[4][4];
    {
        const uint32_t abase = smb + (uint32_t)((w * 16 + (lane & 15)) * 144 + (lane >> 4) * 16);
        #pragma unroll
        for (int kk = 0; kk < 4; kk++) ldm_x4(ah[kk], abase + kk * 32);
    }
    const uint32_t bbase = smb + 9216 +
        (uint32_t)(((lane & 7) + ((lane >> 4) & 1) * 8) * 144 + ((lane >> 3) & 1) * 16);

    float sacc[8][4];
    #pragma unroll
    for (int j = 0; j < 8; j++)
        #pragma unroll
        for (int e = 0; e < 4; e++) sacc[j][e] = 0.f;

    #pragma unroll
    for (int jj = 0; jj < 4; jj++) {
        #pragma unroll
        for (int kk = 0; kk < 4; kk++) {
            uint32_t bhr[4];
            ldm_x4(bhr, bbase + (uint32_t)(jj * 16 * 144 + kk * 32));
            mma16816(sacc[2*jj],   ah[kk][0], ah[kk][1], ah[kk][2], ah[kk][3], bhr[0], bhr[1]);
            mma16816(sacc[2*jj+1], ah[kk][0], ah[kk][1], ah[kk][2], ah[kk][3], bhr[2], bhr[3]);
        }
    }

    const float scale = (which == 0) ? 0.125f * LOG2E : 1.0f;
    __half* Ah = (which == 0) ? g_Qh : (which == 1) ? g_Kh : g_Vh;
    const int b   = m0 >> 11;
    const int ss0 = m0 & 2047;
    const int r0  = w * 16 + (lane >> 2);
    const size_t base0 = (((size_t)b * HH + h) * SS + (ss0 + r0)) * DD;
    const size_t base1 = base0 + (size_t)8 * DD;
    #pragma unroll
    for (int j = 0; j < 8; j++) {
        const int c = j * 8 + 2 * (lane & 3);
        *(uint32_t*)&Ah[base0 + c] = pack2h((sacc[j][0] + bp[c0 + c]) * scale,
                                            (sacc[j][1] + bp[c0 + c + 1]) * scale);
        *(uint32_t*)&Ah[base1 + c] = pack2h((sacc[j][2] + bp[c0 + c]) * scale,
                                            (sacc[j][3] + bp[c0 + c + 1]) * scale);
    }
}

// ---------------------------------------------------------------------------
// Kernel 2: causal flash attention (fp16 HMMA, hi-only operands).
// Exact R13/R16 structure (proven): 2 syncs/tile, CPW1 prefetch pattern.
// 2 CTAs/SM.  grid = (S/128, H, B), block = 256.
// ---------------------------------------------------------------------------
#define SQH 0
#define SKV 18432            // two buffers of 36864 (KH, VH @ 18432 each)
#define ATTN_SMEM (18432 + 2*36864)   // 92160; x2 CTAs = 184320 < 227KB

__global__ void __launch_bounds__(256, 2) attn_kernel() {
    extern __shared__ char smem[];
    const uint32_t smb = smem_u32(smem);

    const int qt = gridDim.x - 1 - blockIdx.x;   // heavy tiles first
    const int h  = blockIdx.y;
    const int b  = blockIdx.z;
    const int q0 = qt * 128;

    const int tid  = threadIdx.x;
    const int w    = tid >> 5;
    const int lane = tid & 31;

    const size_t bh = (size_t)b * HH + h;
    const __half* Qh = g_Qh + (bh * SS + q0) * DD;
    const __half* Kh = g_Kh + bh * SS * DD;
    const __half* Vh = g_Vh + bh * SS * DD;

    const int ktmax = qt;   // 128-key tiles, kt <= qt

    // prefetch K/V tile 0 into buffer 0 (K: 128x64, V: 128x64)
    {
        const uint32_t base = smb + SKV;
        for (int idx = tid; idx < 2048; idx += 256) {
            int arr = idx >> 10, rem = idx & 1023, r = rem >> 3, ch = rem & 7;
            const __half* src = (arr == 0) ? (Kh + (size_t)r * DD + ch * 8)
                                           : (Vh + (size_t)r * DD + ch * 8);
            CPA(base + arr * 18432 + r * 144 + ch * 16, src);
        }
        CPC();
    }

    // load Q tile (hi only)
    for (int idx = tid; idx < 1024; idx += 256) {
        int r = idx >> 3, ch = idx & 7;
        *(uint4*)(smem + SQH + r * 144 + ch * 16) = *(const uint4*)(Qh + (size_t)r * DD + ch * 8);
    }
    __syncthreads();

    uint32_t qh[4][4];
    {
        const uint32_t qbase = smb + SQH + (uint32_t)((w * 16 + (lane & 15)) * 144 + (lane >> 4) * 16);
        #pragma unroll
        for (int kk = 0; kk < 4; kk++) ldm_x4(qh[kk], qbase + kk * 32);
    }

    float o[8][4];
    #pragma unroll
    for (int j = 0; j < 8; j++)
        #pragma unroll
        for (int e = 0; e < 4; e++) o[j][e] = 0.f;
    float lacc[4] = {0.f, 0.f, 0.f, 0.f};   // row-sum accumulator (B=ones MMA)
    float m0 = -1e30f, m1 = -1e30f;

    const int rg0  = q0 + w * 16 + (lane >> 2);
    const int wmax = q0 + w * 16 + 15;

    const uint32_t klane = (uint32_t)(((lane & 7) + ((lane >> 4) & 1) * 8) * 144 + ((lane >> 3) & 1) * 16);
    const uint32_t vlane = (uint32_t)(((lane & 7) + ((lane >> 3) & 1) * 8) * 144 + ((lane >> 4) & 1) * 16);

    for (int kt = 0; kt <= ktmax; kt++) {
        const int buf = kt & 1;

        if (kt < ktmax) {
            const int nk0 = (kt + 1) * 128;
            const uint32_t base = smb + SKV + (buf ^ 1) * 36864;
            for (int idx = tid; idx < 2048; idx += 256) {
                int arr = idx >> 10, rem = idx & 1023, r = rem >> 3, ch = rem & 7;
                const __half* src = (arr == 0) ? (Kh + (size_t)(nk0 + r) * DD + ch * 8)
                                               : (Vh + (size_t)(nk0 + r) * DD + ch * 8);
                CPA(base + arr * 18432 + r * 144 + ch * 16, src);
            }
            CPC();
            CPW1();
        } else {
            CPW0();
        }
        __syncthreads();

        const uint32_t kvb = smb + SKV + buf * 36864;

        #pragma unroll
        for (int hf = 0; hf < 2; hf++) {
            const int khalf0 = kt * 128 + hf * 64;
            int jjn = (wmax >= khalf0) ? (((wmax - khalf0) >> 4) + 1) : 0;
            if (jjn > 4) jjn = 4;
            if (jjn == 0) continue;

            const uint32_t kbase = kvb + (uint32_t)(hf * 64 * 144) + klane;
            const uint32_t vbase = kvb + 18432 + (uint32_t)(hf * 64 * 144) + vlane;

            // ---- S = Qh Kh^T ----
            float sacc[8][4];
            #pragma unroll
            for (int j = 0; j < 8; j++)
                #pragma unroll
                for (int e = 0; e < 4; e++) sacc[j][e] = 0.f;

            #pragma unroll
            for (int jj = 0; jj < 4; jj++) {
                if (jj >= jjn) break;
                #pragma unroll
                for (int kk = 0; kk < 4; kk++) {
                    uint32_t bhr[4];
                    ldm_x4(bhr, kbase + (uint32_t)(jj * 16 * 144 + kk * 32));
                    mma16816(sacc[2*jj],   qh[kk][0], qh[kk][1], qh[kk][2], qh[kk][3], bhr[0], bhr[1]);
                    mma16816(sacc[2*jj+1], qh[kk][0], qh[kk][1], qh[kk][2], qh[kk][3], bhr[2], bhr[3]);
                }
            }
            // blank untouched groups (so max is unaffected; exp gives 0)
            #pragma unroll
            for (int j = 0; j < 8; j++)
                if (j >= 2 * jjn) {
                    sacc[j][0] = sacc[j][1] = sacc[j][2] = sacc[j][3] = -1e30f;
                }

            // ---- causal element mask (only if this half straddles diag) ----
            if (khalf0 + 63 > rg0) {
                #pragma unroll
                for (int j = 0; j < 8; j++) {
                    const int cbase = khalf0 + j * 8 + 2 * (lane & 3);
                    if (cbase     > rg0)     sacc[j][0] = -1e30f;
                    if (cbase + 1 > rg0)     sacc[j][1] = -1e30f;
                    if (cbase     > rg0 + 8) sacc[j][2] = -1e30f;
                    if (cbase + 1 > rg0 + 8) sacc[j][3] = -1e30f;
                }
            }

            // ---- online softmax (base-2), exp in half2 ----
            float mx0 = -1e30f, mx1 = -1e30f;
            #pragma unroll
            for (int j = 0; j < 8; j++) {
                mx0 = fmaxf(mx0, fmaxf(sacc[j][0], sacc[j][1]));
                mx1 = fmaxf(mx1, fmaxf(sacc[j][2], sacc[j][3]));
            }
            mx0 = fmaxf(mx0, __shfl_xor_sync(0xffffffffu, mx0, 1));
            mx0 = fmaxf(mx0, __shfl_xor_sync(0xffffffffu, mx0, 2));
            mx1 = fmaxf(mx1, __shfl_xor_sync(0xffffffffu, mx1, 1));
            mx1 = fmaxf(mx1, __shfl_xor_sync(0xffffffffu, mx1, 2));

            const float nm0 = fmaxf(m0, mx0);
            const float nm1 = fmaxf(m1, mx1);
            const float corr0 = ex2(m0 - nm0);
            const float corr1 = ex2(m1 - nm1);
            m0 = nm0; m1 = nm1;

            uint32_t ph[8][2];
            #pragma unroll
            for (int j = 0; j < 8; j++) {
                ph[j][0] = h2ex2(pack2h(sacc[j][0] - nm0, sacc[j][1] - nm0));
                ph[j][1] = h2ex2(pack2h(sacc[j][2] - nm1, sacc[j][3] - nm1));
            }

            // rescale running O and l
            #pragma unroll
            for (int j = 0; j < 8; j++) {
                o[j][0] *= corr0; o[j][1] *= corr0;
                o[j][2] *= corr1; o[j][3] *= corr1;
            }
            lacc[0] *= corr0; lacc[1] *= corr0;
            lacc[2] *= corr1; lacc[3] *= corr1;

            // ---- O += Ph Vh;  l += Ph @ ones ----
            #pragma unroll
            for (int kk = 0; kk < 4; kk++) {
                if (kk >= jjn) break;
                mma16816(lacc, ph[2*kk][0], ph[2*kk][1], ph[2*kk+1][0], ph[2*kk+1][1], ONES2H, ONES2H);
                #pragma unroll
                for (int dd = 0; dd < 4; dd++) {
                    uint32_t vh[4];
                    ldm_x4_t(vh, vbase + (uint32_t)(kk * 16 * 144 + dd * 32));
                    mma16816(o[2*dd],   ph[2*kk][0], ph[2*kk][1], ph[2*kk+1][0], ph[2*kk+1][1], vh[0], vh[1]);
                    mma16816(o[2*dd+1], ph[2*kk][0], ph[2*kk][1], ph[2*kk+1][0], ph[2*kk+1][1], vh[2], vh[3]);
                }
            }
        }
        __syncthreads();
    }

    // ---- epilogue: normalize, write fp16 (hi only) [B,S,HID] ----
    const float inv0 = 1.f / lacc[0];
    const float inv1 = 1.f / lacc[2];
    const size_t db0 = ((size_t)b * SS + rg0) * HID + h * 64;
    const size_t db1 = db0 + (size_t)8 * HID;
    #pragma unroll
    for (int j = 0; j < 8; j++) {
        const int c = j * 8 + 2 * (lane & 3);
        *(uint32_t*)&g_attnh[db0 + c] = pack2h(o[j][0] * inv0, o[j][1] * inv0);
        *(uint32_t*)&g_attnh[db1 + c] = pack2h(o[j][2] * inv1, o[j][3] * inv1);
    }
}

// ---------------------------------------------------------------------------
// Kernel 3: output projection via HMMA: Ah @ Woh + bo (single combo).
// R13 sync/prefetch pattern.  grid = BS/64, block = 128.  K=1024, 16 steps.
// ---------------------------------------------------------------------------
// per buffer: AH, WH @ 9216 each = 18432; two buffers = 36864.
#define OPROJ_SMEM (2 * 18432)
__global__ void __launch_bounds__(128) oproj_mma_kernel(const float* __restrict__ bo,
                                                        float* __restrict__ out) {
    extern __shared__ char smem[];
    const uint32_t smb = smem_u32(smem);

    const int m0  = blockIdx.x * 64;
    const int tid = threadIdx.x;
    const int w   = tid >> 5;
    const int lane = tid & 31;

    {
        const uint32_t base = smb;
        for (int idx = tid; idx < 1024; idx += 128) {
            int arr = idx >> 9, rem = idx & 511, r = rem >> 3, ch = rem & 7;
            const __half* src = (arr == 0) ? (g_attnh + (size_t)(m0 + r) * HID + ch * 8)
                                           : (g_WoTh + (size_t)r * HID + ch * 8);
            CPA(base + arr * 9216 + r * 144 + ch * 16, src);
        }
        CPC();
    }

    float sacc[8][4];
    #pragma unroll
    for (int j = 0; j < 8; j++)
        #pragma unroll
        for (int e = 0; e < 4; e++) sacc[j][e] = 0.f;

    const uint32_t a_off = (uint32_t)((w * 16 + (lane & 15)) * 144 + (lane >> 4) * 16);
    const uint32_t b_off = (uint32_t)(((lane & 7) + ((lane >> 4) & 1) * 8) * 144 + ((lane >> 3) & 1) * 16);

    for (int kt = 0; kt < 16; kt++) {
        const int buf = kt & 1;
        if (kt < 15) {
            const int nk0 = (kt + 1) * 64;
            const uint32_t base = smb + (buf ^ 1) * 18432;
            for (int idx = tid; idx < 1024; idx += 128) {
                int arr = idx >> 9, rem = idx & 511, r = rem >> 3, ch = rem & 7;
                const __half* src = (arr == 0) ? (g_attnh + (size_t)(m0 + r) * HID + nk0 + ch * 8)
                                               : (g_WoTh + (size_t)r * HID + nk0 + ch * 8);
                CPA(base + arr * 9216 + r * 144 + ch * 16, src);
            }
            CPC();
            CPW1();
        } else {
            CPW0();
        }
        __syncthreads();

        const uint32_t bb = smb + buf * 18432;
        const uint32_t abase = bb + a_off;
        const uint32_t bbase = bb + 9216 + b_off;

        #pragma unroll
        for (int kk = 0; kk < 4; kk++) {
            uint32_t ah[4];
            ldm_x4(ah, abase + kk * 32);
            #pragma unroll
            for (int jj = 0; jj < 4; jj++) {
                uint32_t bhr[4];
                ldm_x4(bhr, bbase + (uint32_t)(jj * 16 * 144 + kk * 32));
                mma16816(sacc[2*jj],   ah[0], ah[1], ah[2], ah[3], bhr[0], bhr[1]);
                mma16816(sacc[2*jj+1], ah[0], ah[1], ah[2], ah[3], bhr[2], bhr[3]);
            }
        }
        __syncthreads();
    }

    const int r0 = w * 16 + (lane >> 2);
    #pragma unroll
    for (int j = 0; j < 8; j++) {
        const int c = j * 8 + 2 * (lane & 3);
        out[(size_t)(m0 + r0) * DD + c]     = sacc[j][0] + bo[c];
        out[(size_t)(m0 + r0) * DD + c + 1] = sacc[j][1] + bo[c + 1];
        out[(size_t)(m0 + r0 + 8) * DD + c]     = sacc[j][2] + bo[c];
        out[(size_t)(m0 + r0 + 8) * DD + c + 1] = sacc[j][3] + bo[c + 1];
    }
}

// ---------------------------------------------------------------------------
extern "C" void kernel_launch(void* const* d_in, const int* in_sizes, int n_in,
                              void* d_out, int out_size) {
    (void)in_sizes; (void)n_in; (void)out_size;
    const float* x  = (const float*)d_in[0];
    const float* Wq = (const float*)d_in[1];
    const float* bq = (const float*)d_in[2];
    const float* Wk = (const float*)d_in[3];
    const float* bk = (const float*)d_in[4];
    const float* Wv = (const float*)d_in[5];
    const float* bv = (const float*)d_in[6];
    const float* Wo = (const float*)d_in[7];
    const float* bo = (const float*)d_in[8];
    float* out = (float*)d_out;

    prep_kernel<<<1024, 256>>>(x, Wq, Wk, Wv, Wo);

    qkv_mma_kernel<<<dim3(BS / 64, HID / 64, 3), 128>>>(bq, bk, bv);

    cudaFuncSetAttribute(attn_kernel, cudaFuncAttributeMaxDynamicSharedMemorySize, ATTN_SMEM);
    attn_kernel<<<dim3(SS / 128, HH, BB), 256, ATTN_SMEM>>>();

    cudaFuncSetAttribute(oproj_mma_kernel, cudaFuncAttributeMaxDynamicSharedMemorySize, OPROJ_SMEM);
    oproj_mma_kernel<<<BS / 64, 128, OPROJ_SMEM>>>(bo, out);
}